// round 14
// baseline (speedup 1.0000x reference)
#include <cuda_runtime.h>
#include <cuda_fp16.h>
#include <stdint.h>

#define DIM 512
#define NN 25000
#define NE 400000
#define BN_EPS 1e-5f

// ---------------- scratch (device globals; no runtime alloc) ----------------
__device__ __half g_eaf16[(size_t)NE * DIM];
__device__ __half g_weT16[DIM * DIM];
__device__ __half g_w1T16[DIM * DIM];
__device__ __half g_w2T16[DIM * DIM];
__device__ float g_aggr[(size_t)NN * DIM];
__device__ __half g_ag16[(size_t)NN * DIM];
__device__ __half g_h116[(size_t)NN * DIM];
__device__ float g_h2[(size_t)NN * DIM];
__device__ float g_sum[DIM], g_sumsq[DIM], g_mean[DIM], g_istd[DIM];

// ---------------- helpers ----------------
__device__ __forceinline__ uint32_t smem_u32(const void* p) {
    uint32_t a;
    asm("{ .reg .u64 t; cvta.to.shared.u64 t, %1; cvt.u32.u64 %0, t; }" : "=r"(a) : "l"(p));
    return a;
}
#define SW128(off) ((off) ^ (((off) >> 3) & 0x70))

__device__ __forceinline__ void cp16(uint32_t s, const void* g) {
    asm volatile("cp.async.cg.shared.global [%0], [%1], 16;" :: "r"(s), "l"(g));
}
__device__ __forceinline__ void ldm4(uint32_t* r, uint32_t a) {
    asm volatile("ldmatrix.sync.aligned.m8n8.x4.shared.b16 {%0,%1,%2,%3}, [%4];"
        : "=r"(r[0]), "=r"(r[1]), "=r"(r[2]), "=r"(r[3]) : "r"(a));
}
__device__ __forceinline__ void mma_f16(float* d, const uint32_t* a, const uint32_t* b) {
    asm volatile("mma.sync.aligned.m16n8k16.row.col.f32.f16.f16.f32 "
        "{%0,%1,%2,%3}, {%4,%5,%6,%7}, {%8,%9}, {%0,%1,%2,%3};"
        : "+f"(d[0]), "+f"(d[1]), "+f"(d[2]), "+f"(d[3])
        : "r"(a[0]), "r"(a[1]), "r"(a[2]), "r"(a[3]), "r"(b[0]), "r"(b[1]));
}
__device__ __forceinline__ void red_v4(float* p, float a, float b, float c, float d) {
    asm volatile("red.global.add.v4.f32 [%0], {%1, %2, %3, %4};"
        :: "l"(p), "f"(a), "f"(b), "f"(c), "f"(d) : "memory");
}

// ---------------- prep kernels ----------------
__global__ __launch_bounds__(256) void tohalf_kernel(const float* __restrict__ src,
                                                     __half* __restrict__ dst, size_t n4)
{
    size_t i = (size_t)blockIdx.x * blockDim.x + threadIdx.x;
    if (i < n4) {
        float4 v = reinterpret_cast<const float4*>(src)[i];
        reinterpret_cast<__half2*>(dst)[2 * i] = __floats2half2_rn(v.x, v.y);
        reinterpret_cast<__half2*>(dst)[2 * i + 1] = __floats2half2_rn(v.z, v.w);
    }
}

__global__ __launch_bounds__(256) void transpose_half_kernel(const float* __restrict__ W,
                                                             __half* __restrict__ d16)
{
    int i = blockIdx.x * blockDim.x + threadIdx.x;   // i = n*512 + k
    if (i < DIM * DIM) {
        int n = i >> 9, k = i & 511;
        d16[i] = __float2half_rn(W[k * DIM + n]);
    }
}

// ---------------- fp16 HMMA GEMM, 256x128 block, 64x64 warp tiles ----------------
// C[M x 512] = A[M x 512] @ B[512 x 512], fp16 in, fp32 accum.
// 256 thr, 8 warps (4m x 2n), warp tile 64x64, 3-stage cp.async pipeline.
// MODE 0: edge: v = relu(acc + bias + x[src]); red.v4(aggr[dst], v)
// MODE 1: v = relu(acc + bias) -> fp16 store
// MODE 2: v = acc + bias -> fp32 store
#define STAGE_BYTES 49152   // A 32K + B 16K

template <int MODE>
__global__ __launch_bounds__(256)
void mma_gemm_kernel(const __half* __restrict__ A,
                     const __half* __restrict__ B,    // transposed [N][K]
                     const float* __restrict__ bias,
                     int M,
                     const float* __restrict__ x,
                     const int* __restrict__ ei,
                     float* __restrict__ outf,
                     __half* __restrict__ outh)
{
    extern __shared__ char smem[];                    // 3 x (A 32K + B 16K)
    const uint32_t sbase = smem_u32(smem);
    const int tid = threadIdx.x;
    const int wid = tid >> 5, lane = tid & 31;
    const int wm = wid & 3, wn = wid >> 2;
    const int row0 = blockIdx.y * 256;
    const int col0 = blockIdx.x * 128;

    float acc[4][8][4];
#pragma unroll
    for (int i = 0; i < 4; i++)
#pragma unroll
        for (int j = 0; j < 8; j++)
#pragma unroll
            for (int k = 0; k < 4; k++) acc[i][j][k] = 0.f;

    auto prefetch = [&](int c, int s) {
        const int k0 = c * 64;
        const uint32_t abase = sbase + (uint32_t)s * STAGE_BYTES;
        const uint32_t bbase = abase + 32768;
        // A: 256 rows x 128B
#pragma unroll
        for (int i = 0; i < 8; i++) {
            const int u = i * 256 + tid;              // 0..2047
            const int row = u >> 3, s16 = u & 7;
            int ar = row0 + row; if (ar >= M) ar = M - 1;
            cp16(abase + SW128((uint32_t)(row * 128 + s16 * 16)),
                 A + (size_t)ar * DIM + k0 + s16 * 8);
        }
        // B: 128 rows x 128B
#pragma unroll
        for (int i = 0; i < 4; i++) {
            const int u = i * 256 + tid;              // 0..1023
            const int row = u >> 3, s16 = u & 7;
            cp16(bbase + SW128((uint32_t)(row * 128 + s16 * 16)),
                 B + (size_t)(col0 + row) * DIM + k0 + s16 * 8);
        }
        asm volatile("cp.async.commit_group;" ::: "memory");
    };

    auto compute = [&](int s) {
        const uint32_t abase = sbase + (uint32_t)s * STAGE_BYTES;
        const uint32_t bbase = abase + 32768;
#pragma unroll
        for (int kk = 0; kk < 4; kk++) {
            uint32_t a[4][4];
#pragma unroll
            for (int mt = 0; mt < 4; mt++) {
                const int r = wm * 64 + mt * 16 + (lane & 15);
                const uint32_t kb = (uint32_t)(kk * 32 + (lane >> 4) * 16);
                ldm4(a[mt], abase + SW128((uint32_t)(r * 128) + kb));
            }
            uint32_t b[8][2];
#pragma unroll
            for (int g = 0; g < 4; g++) {
                const int grp = lane >> 3;
                const int r = wn * 64 + g * 16 + (grp >> 1) * 8 + (lane & 7);
                const uint32_t kb = (uint32_t)(kk * 32 + (grp & 1) * 16);
                uint32_t t[4];
                ldm4(t, bbase + SW128((uint32_t)(r * 128) + kb));
                b[2 * g][0] = t[0]; b[2 * g][1] = t[1];
                b[2 * g + 1][0] = t[2]; b[2 * g + 1][1] = t[3];
            }
#pragma unroll
            for (int mt = 0; mt < 4; mt++)
#pragma unroll
                for (int nt = 0; nt < 8; nt++)
                    mma_f16(acc[mt][nt], a[mt], b[nt]);
        }
    };

    // 3-stage pipeline, prefetch depth 2, one sync per chunk.
    prefetch(0, 0);
    prefetch(1, 1);
    int sc = 0, sp = 2;
    for (int c = 0; c < 8; c++) {
        if (c == 7) {
            asm volatile("cp.async.wait_group 0;" ::: "memory");
        } else {
            asm volatile("cp.async.wait_group 1;" ::: "memory");
        }
        __syncthreads();
        if (c < 6) prefetch(c + 2, sp);
        compute(sc);
        sc = (sc == 2) ? 0 : sc + 1;
        sp = (sp == 2) ? 0 : sp + 1;
    }

    // ---------------- epilogue (direct from fragments) ----------------
    const int colbase = col0 + wn * 64;
#pragma unroll
    for (int mt = 0; mt < 4; mt++) {
#pragma unroll
        for (int h = 0; h < 2; h++) {
            const int r = row0 + wm * 64 + mt * 16 + h * 8 + (lane >> 2);
            if (r < M) {
                if (MODE == 0) {
                    const int src = ei[r];
                    const int dst = ei[NE + r];
                    const float* xr = x + (size_t)src * DIM;
                    float* ap = outf + (size_t)dst * DIM;
#pragma unroll
                    for (int nt = 0; nt < 8; nt++) {
                        const int c = colbase + nt * 8 + (lane & 3) * 2;
                        float2 xv = *reinterpret_cast<const float2*>(xr + c);
                        float v0 = fmaxf(acc[mt][nt][h * 2 + 0] + bias[c] + xv.x, 0.f);
                        float v1 = fmaxf(acc[mt][nt][h * 2 + 1] + bias[c + 1] + xv.y, 0.f);
                        float p0 = __shfl_xor_sync(0xFFFFFFFFu, v0, 1);
                        float p1 = __shfl_xor_sync(0xFFFFFFFFu, v1, 1);
                        if ((lane & 1) == 0)
                            red_v4(ap + c, v0, v1, p0, p1);
                    }
                } else if (MODE == 1) {
#pragma unroll
                    for (int nt = 0; nt < 8; nt++) {
                        const int c = colbase + nt * 8 + (lane & 3) * 2;
                        float v0 = fmaxf(acc[mt][nt][h * 2 + 0] + bias[c], 0.f);
                        float v1 = fmaxf(acc[mt][nt][h * 2 + 1] + bias[c + 1], 0.f);
                        *reinterpret_cast<__half2*>(outh + (size_t)r * DIM + c) =
                            __floats2half2_rn(v0, v1);
                    }
                } else {
#pragma unroll
                    for (int nt = 0; nt < 8; nt++) {
                        const int c = colbase + nt * 8 + (lane & 3) * 2;
                        float2 v;
                        v.x = acc[mt][nt][h * 2 + 0] + bias[c];
                        v.y = acc[mt][nt][h * 2 + 1] + bias[c + 1];
                        *reinterpret_cast<float2*>(outf + (size_t)r * DIM + c) = v;
                    }
                }
            }
        }
    }
}

// ---------------- BN kernels ----------------
__global__ __launch_bounds__(256) void bn_stats_kernel()
{
    const int t = threadIdx.x;
    float sx = 0.f, sy = 0.f, qx = 0.f, qy = 0.f;
    const float2* p = reinterpret_cast<const float2*>(g_h2) + t;
    for (int r = blockIdx.x; r < NN; r += gridDim.x) {
        float2 v = p[(size_t)r * 256];
        sx += v.x; sy += v.y;
        qx = fmaf(v.x, v.x, qx); qy = fmaf(v.y, v.y, qy);
    }
    atomicAdd(&g_sum[2 * t], sx);
    atomicAdd(&g_sum[2 * t + 1], sy);
    atomicAdd(&g_sumsq[2 * t], qx);
    atomicAdd(&g_sumsq[2 * t + 1], qy);
}

__global__ void bn_finalize_kernel()
{
    int c = blockIdx.x * blockDim.x + threadIdx.x;
    if (c < DIM) {
        float mean = g_sum[c] * (1.f / NN);
        float var = g_sumsq[c] * (1.f / NN) - mean * mean;
        g_mean[c] = mean;
        g_istd[c] = rsqrtf(var + BN_EPS);
    }
}

__global__ __launch_bounds__(256)
void bn_apply_kernel(const float* __restrict__ gamma,
                     const float* __restrict__ beta,
                     float* __restrict__ out)
{
    int idx = blockIdx.x * blockDim.x + threadIdx.x;
    if (idx >= NN * DIM / 4) return;
    const int c = (idx & (DIM / 4 - 1)) * 4;
    float4 h = reinterpret_cast<const float4*>(g_h2)[idx];
    float4 m = *reinterpret_cast<const float4*>(&g_mean[c]);
    float4 is = *reinterpret_cast<const float4*>(&g_istd[c]);
    float4 ga = *reinterpret_cast<const float4*>(&gamma[c]);
    float4 be = *reinterpret_cast<const float4*>(&beta[c]);
    float4 o;
    o.x = (h.x - m.x) * is.x * ga.x + be.x;
    o.y = (h.y - m.y) * is.y * ga.y + be.y;
    o.z = (h.z - m.z) * is.z * ga.z + be.z;
    o.w = (h.w - m.w) * is.w * ga.w + be.w;
    reinterpret_cast<float4*>(out)[idx] = o;
}

// ---------------- launch ----------------
#define SMEM_GEMM (3 * STAGE_BYTES)   // 147456

extern "C" void kernel_launch(void* const* d_in, const int* in_sizes, int n_in,
                              void* d_out, int out_size)
{
    const float* x     = (const float*)d_in[0];
    const int*   ei    = (const int*)d_in[1];
    const float* eattr = (const float*)d_in[2];
    const float* We    = (const float*)d_in[3];
    const float* be    = (const float*)d_in[4];
    const float* W1    = (const float*)d_in[5];
    const float* b1    = (const float*)d_in[6];
    const float* W2    = (const float*)d_in[7];
    const float* b2    = (const float*)d_in[8];
    const float* gamma = (const float*)d_in[9];
    const float* beta  = (const float*)d_in[10];
    float* out = (float*)d_out;

    void *eaf, *weT, *w1T, *w2T, *aggr, *ag16, *h116, *h2, *sum_p, *sq_p;
    cudaGetSymbolAddress(&eaf, g_eaf16);
    cudaGetSymbolAddress(&weT, g_weT16);
    cudaGetSymbolAddress(&w1T, g_w1T16);
    cudaGetSymbolAddress(&w2T, g_w2T16);
    cudaGetSymbolAddress(&aggr, g_aggr);
    cudaGetSymbolAddress(&ag16, g_ag16);
    cudaGetSymbolAddress(&h116, g_h116);
    cudaGetSymbolAddress(&h2, g_h2);
    cudaGetSymbolAddress(&sum_p, g_sum);
    cudaGetSymbolAddress(&sq_p, g_sumsq);

    cudaFuncSetAttribute((const void*)mma_gemm_kernel<0>, cudaFuncAttributeMaxDynamicSharedMemorySize, SMEM_GEMM);
    cudaFuncSetAttribute((const void*)mma_gemm_kernel<1>, cudaFuncAttributeMaxDynamicSharedMemorySize, SMEM_GEMM);
    cudaFuncSetAttribute((const void*)mma_gemm_kernel<2>, cudaFuncAttributeMaxDynamicSharedMemorySize, SMEM_GEMM);

    // aggr = x (GIN eps=0); zero BN accumulators
    cudaMemcpyAsync(aggr, x, sizeof(float) * (size_t)NN * DIM, cudaMemcpyDeviceToDevice);
    cudaMemsetAsync(sum_p, 0, DIM * sizeof(float));
    cudaMemsetAsync(sq_p, 0, DIM * sizeof(float));

    // prep: eattr -> fp16; We/W1/W2 transposed -> fp16
    {
        size_t n4 = (size_t)NE * DIM / 4;
        tohalf_kernel<<<(unsigned)((n4 + 255) / 256), 256>>>(eattr, (__half*)eaf, n4);
        transpose_half_kernel<<<(DIM * DIM + 255) / 256, 256>>>(We, (__half*)weT);
        transpose_half_kernel<<<(DIM * DIM + 255) / 256, 256>>>(W1, (__half*)w1T);
        transpose_half_kernel<<<(DIM * DIM + 255) / 256, 256>>>(W2, (__half*)w2T);
    }

    // edge GEMM (fp16) + gather + relu + vector-red scatter-add
    const int erb = (NE + 255) / 256;     // 1563
    mma_gemm_kernel<0><<<dim3(4, erb), 256, SMEM_GEMM>>>(
        (const __half*)eaf, (const __half*)weT, be, NE, x, ei, (float*)aggr, nullptr);

    // aggr -> fp16
    {
        size_t n4 = (size_t)NN * DIM / 4;
        tohalf_kernel<<<(unsigned)((n4 + 255) / 256), 256>>>((const float*)aggr, (__half*)ag16, n4);
    }

    const int nrb = (NN + 255) / 256;     // 98
    // h1 = relu(aggr @ W1 + b1) -> fp16
    mma_gemm_kernel<1><<<dim3(4, nrb), 256, SMEM_GEMM>>>(
        (const __half*)ag16, (const __half*)w1T, b1, NN, nullptr, nullptr, nullptr, (__half*)h116);

    // h2 = h1 @ W2 + b2 -> fp32
    mma_gemm_kernel<2><<<dim3(4, nrb), 256, SMEM_GEMM>>>(
        (const __half*)h116, (const __half*)w2T, b2, NN, nullptr, nullptr, (float*)h2, nullptr);

    bn_stats_kernel<<<64, 256>>>();
    bn_finalize_kernel<<<2, 256>>>();

    const int n4 = NN * DIM / 4;
    bn_apply_kernel<<<(n4 + 255) / 256, 256>>>(gamma, beta, out);
}

// round 15
// speedup vs baseline: 1.0981x; 1.0981x over previous
#include <cuda_runtime.h>
#include <cuda_fp16.h>
#include <stdint.h>

#define DIM 512
#define NN 25000
#define NE 400000
#define BN_EPS 1e-5f

// ---------------- scratch (device globals; no runtime alloc) ----------------
__device__ __half g_eaf16[(size_t)NE * DIM];
__device__ __half g_weT16[DIM * DIM];
__device__ __half g_w1T16[DIM * DIM];
__device__ __half g_w2T16[DIM * DIM];
__device__ float g_aggr[(size_t)NN * DIM];
__device__ __half g_ag16[(size_t)NN * DIM];
__device__ __half g_h116[(size_t)NN * DIM];
__device__ float g_h2[(size_t)NN * DIM];
__device__ float g_sum[DIM], g_sumsq[DIM], g_mean[DIM], g_istd[DIM];

// ---------------- helpers ----------------
__device__ __forceinline__ uint32_t smem_u32(const void* p) {
    uint32_t a;
    asm("{ .reg .u64 t; cvta.to.shared.u64 t, %1; cvt.u32.u64 %0, t; }" : "=r"(a) : "l"(p));
    return a;
}
#define SW128(off) ((off) ^ (((off) >> 3) & 0x70))

__device__ __forceinline__ void cp16(uint32_t s, const void* g) {
    asm volatile("cp.async.cg.shared.global [%0], [%1], 16;" :: "r"(s), "l"(g));
}
__device__ __forceinline__ void ldm4(uint32_t* r, uint32_t a) {
    asm volatile("ldmatrix.sync.aligned.m8n8.x4.shared.b16 {%0,%1,%2,%3}, [%4];"
        : "=r"(r[0]), "=r"(r[1]), "=r"(r[2]), "=r"(r[3]) : "r"(a));
}
__device__ __forceinline__ void mma_f16(float* d, const uint32_t* a, const uint32_t* b) {
    asm volatile("mma.sync.aligned.m16n8k16.row.col.f32.f16.f16.f32 "
        "{%0,%1,%2,%3}, {%4,%5,%6,%7}, {%8,%9}, {%0,%1,%2,%3};"
        : "+f"(d[0]), "+f"(d[1]), "+f"(d[2]), "+f"(d[3])
        : "r"(a[0]), "r"(a[1]), "r"(a[2]), "r"(a[3]), "r"(b[0]), "r"(b[1]));
}
__device__ __forceinline__ void red_v4(float* p, float a, float b, float c, float d) {
    asm volatile("red.global.add.v4.f32 [%0], {%1, %2, %3, %4};"
        :: "l"(p), "f"(a), "f"(b), "f"(c), "f"(d) : "memory");
}

// ---------------- prep kernels ----------------
__global__ __launch_bounds__(256) void tohalf_kernel(const float* __restrict__ src,
                                                     __half* __restrict__ dst, size_t n4)
{
    size_t i = (size_t)blockIdx.x * blockDim.x + threadIdx.x;
    if (i < n4) {
        float4 v = reinterpret_cast<const float4*>(src)[i];
        reinterpret_cast<__half2*>(dst)[2 * i] = __floats2half2_rn(v.x, v.y);
        reinterpret_cast<__half2*>(dst)[2 * i + 1] = __floats2half2_rn(v.z, v.w);
    }
}

__global__ __launch_bounds__(256) void transpose_half_kernel(const float* __restrict__ W,
                                                             __half* __restrict__ d16)
{
    int i = blockIdx.x * blockDim.x + threadIdx.x;   // i = n*512 + k
    if (i < DIM * DIM) {
        int n = i >> 9, k = i & 511;
        d16[i] = __float2half_rn(W[k * DIM + n]);
    }
}

// ---------------- fp16 HMMA GEMM: 128x128 block, 128 thr, 64x64 warp tiles ----------------
// 4 warps (2m x 2n), 3-stage cp.async pipeline, 2 CTAs/SM.
// MODE 0: edge: v = relu(acc + bias + x[src]); red.v4(aggr[dst], v)
// MODE 1: v = relu(acc + bias) -> fp16 store
// MODE 2: v = acc + bias -> fp32 store
#define STAGE_BYTES 32768   // A 16K + B 16K

template <int MODE>
__global__ __launch_bounds__(128)
void mma_gemm_kernel(const __half* __restrict__ A,
                     const __half* __restrict__ B,    // transposed [N][K]
                     const float* __restrict__ bias,
                     int M,
                     const float* __restrict__ x,
                     const int* __restrict__ ei,
                     float* __restrict__ outf,
                     __half* __restrict__ outh)
{
    extern __shared__ char smem[];                    // 3 x (A 16K + B 16K)
    const uint32_t sbase = smem_u32(smem);
    const int tid = threadIdx.x;
    const int wid = tid >> 5, lane = tid & 31;
    const int wm = wid & 1, wn = wid >> 1;
    const int row0 = blockIdx.y * 128;
    const int col0 = blockIdx.x * 128;

    float acc[4][8][4];
#pragma unroll
    for (int i = 0; i < 4; i++)
#pragma unroll
        for (int j = 0; j < 8; j++)
#pragma unroll
            for (int k = 0; k < 4; k++) acc[i][j][k] = 0.f;

    auto prefetch = [&](int c, int s) {
        const int k0 = c * 64;
        const uint32_t abase = sbase + (uint32_t)s * STAGE_BYTES;
        const uint32_t bbase = abase + 16384;
#pragma unroll
        for (int i = 0; i < 8; i++) {
            const int u = i * 128 + tid;              // 0..1023
            const int row = u >> 3, s16 = u & 7;
            const uint32_t so = SW128((uint32_t)(row * 128 + s16 * 16));
            int ar = row0 + row; if (ar >= M) ar = M - 1;
            cp16(abase + so, A + (size_t)ar * DIM + k0 + s16 * 8);
            cp16(bbase + so, B + (size_t)(col0 + row) * DIM + k0 + s16 * 8);
        }
        asm volatile("cp.async.commit_group;" ::: "memory");
    };

    auto compute = [&](int s) {
        const uint32_t abase = sbase + (uint32_t)s * STAGE_BYTES;
        const uint32_t bbase = abase + 16384;
#pragma unroll
        for (int kk = 0; kk < 4; kk++) {
            uint32_t a[4][4];
#pragma unroll
            for (int mt = 0; mt < 4; mt++) {
                const int r = wm * 64 + mt * 16 + (lane & 15);
                const uint32_t kb = (uint32_t)(kk * 32 + (lane >> 4) * 16);
                ldm4(a[mt], abase + SW128((uint32_t)(r * 128) + kb));
            }
            uint32_t b[8][2];
#pragma unroll
            for (int g = 0; g < 4; g++) {
                const int grp = lane >> 3;
                const int r = wn * 64 + g * 16 + (grp >> 1) * 8 + (lane & 7);
                const uint32_t kb = (uint32_t)(kk * 32 + (grp & 1) * 16);
                uint32_t t[4];
                ldm4(t, bbase + SW128((uint32_t)(r * 128) + kb));
                b[2 * g][0] = t[0]; b[2 * g][1] = t[1];
                b[2 * g + 1][0] = t[2]; b[2 * g + 1][1] = t[3];
            }
#pragma unroll
            for (int mt = 0; mt < 4; mt++)
#pragma unroll
                for (int nt = 0; nt < 8; nt++)
                    mma_f16(acc[mt][nt], a[mt], b[nt]);
        }
    };

    // 3-stage pipeline, prefetch depth 2, one sync per chunk.
    prefetch(0, 0);
    prefetch(1, 1);
    int sc = 0, sp = 2;
    for (int c = 0; c < 8; c++) {
        if (c == 7) {
            asm volatile("cp.async.wait_group 0;" ::: "memory");
        } else {
            asm volatile("cp.async.wait_group 1;" ::: "memory");
        }
        __syncthreads();
        if (c < 6) prefetch(c + 2, sp);
        compute(sc);
        sc = (sc == 2) ? 0 : sc + 1;
        sp = (sp == 2) ? 0 : sp + 1;
    }

    // ---------------- epilogue (direct from fragments) ----------------
    const int colbase = col0 + wn * 64;
#pragma unroll
    for (int mt = 0; mt < 4; mt++) {
#pragma unroll
        for (int h = 0; h < 2; h++) {
            const int r = row0 + wm * 64 + mt * 16 + h * 8 + (lane >> 2);
            if (r < M) {
                if (MODE == 0) {
                    const int src = ei[r];
                    const int dst = ei[NE + r];
                    const float* xr = x + (size_t)src * DIM;
                    float* ap = outf + (size_t)dst * DIM;
#pragma unroll
                    for (int nt = 0; nt < 8; nt++) {
                        const int c = colbase + nt * 8 + (lane & 3) * 2;
                        float2 xv = *reinterpret_cast<const float2*>(xr + c);
                        float v0 = fmaxf(acc[mt][nt][h * 2 + 0] + bias[c] + xv.x, 0.f);
                        float v1 = fmaxf(acc[mt][nt][h * 2 + 1] + bias[c + 1] + xv.y, 0.f);
                        float p0 = __shfl_xor_sync(0xFFFFFFFFu, v0, 1);
                        float p1 = __shfl_xor_sync(0xFFFFFFFFu, v1, 1);
                        if ((lane & 1) == 0)
                            red_v4(ap + c, v0, v1, p0, p1);
                    }
                } else if (MODE == 1) {
#pragma unroll
                    for (int nt = 0; nt < 8; nt++) {
                        const int c = colbase + nt * 8 + (lane & 3) * 2;
                        float v0 = fmaxf(acc[mt][nt][h * 2 + 0] + bias[c], 0.f);
                        float v1 = fmaxf(acc[mt][nt][h * 2 + 1] + bias[c + 1], 0.f);
                        *reinterpret_cast<__half2*>(outh + (size_t)r * DIM + c) =
                            __floats2half2_rn(v0, v1);
                    }
                } else {
#pragma unroll
                    for (int nt = 0; nt < 8; nt++) {
                        const int c = colbase + nt * 8 + (lane & 3) * 2;
                        float2 v;
                        v.x = acc[mt][nt][h * 2 + 0] + bias[c];
                        v.y = acc[mt][nt][h * 2 + 1] + bias[c + 1];
                        *reinterpret_cast<float2*>(outf + (size_t)r * DIM + c) = v;
                    }
                }
            }
        }
    }
}

// ---------------- BN kernels ----------------
__global__ __launch_bounds__(256) void bn_stats_kernel()
{
    const int t = threadIdx.x;
    float sx = 0.f, sy = 0.f, qx = 0.f, qy = 0.f;
    const float2* p = reinterpret_cast<const float2*>(g_h2) + t;
    for (int r = blockIdx.x; r < NN; r += gridDim.x) {
        float2 v = p[(size_t)r * 256];
        sx += v.x; sy += v.y;
        qx = fmaf(v.x, v.x, qx); qy = fmaf(v.y, v.y, qy);
    }
    atomicAdd(&g_sum[2 * t], sx);
    atomicAdd(&g_sum[2 * t + 1], sy);
    atomicAdd(&g_sumsq[2 * t], qx);
    atomicAdd(&g_sumsq[2 * t + 1], qy);
}

__global__ void bn_finalize_kernel()
{
    int c = blockIdx.x * blockDim.x + threadIdx.x;
    if (c < DIM) {
        float mean = g_sum[c] * (1.f / NN);
        float var = g_sumsq[c] * (1.f / NN) - mean * mean;
        g_mean[c] = mean;
        g_istd[c] = rsqrtf(var + BN_EPS);
    }
}

__global__ __launch_bounds__(256)
void bn_apply_kernel(const float* __restrict__ gamma,
                     const float* __restrict__ beta,
                     float* __restrict__ out)
{
    int idx = blockIdx.x * blockDim.x + threadIdx.x;
    if (idx >= NN * DIM / 4) return;
    const int c = (idx & (DIM / 4 - 1)) * 4;
    float4 h = reinterpret_cast<const float4*>(g_h2)[idx];
    float4 m = *reinterpret_cast<const float4*>(&g_mean[c]);
    float4 is = *reinterpret_cast<const float4*>(&g_istd[c]);
    float4 ga = *reinterpret_cast<const float4*>(&gamma[c]);
    float4 be = *reinterpret_cast<const float4*>(&beta[c]);
    float4 o;
    o.x = (h.x - m.x) * is.x * ga.x + be.x;
    o.y = (h.y - m.y) * is.y * ga.y + be.y;
    o.z = (h.z - m.z) * is.z * ga.z + be.z;
    o.w = (h.w - m.w) * is.w * ga.w + be.w;
    reinterpret_cast<float4*>(out)[idx] = o;
}

// ---------------- launch ----------------
#define SMEM_GEMM (3 * STAGE_BYTES)   // 98304

extern "C" void kernel_launch(void* const* d_in, const int* in_sizes, int n_in,
                              void* d_out, int out_size)
{
    const float* x     = (const float*)d_in[0];
    const int*   ei    = (const int*)d_in[1];
    const float* eattr = (const float*)d_in[2];
    const float* We    = (const float*)d_in[3];
    const float* be    = (const float*)d_in[4];
    const float* W1    = (const float*)d_in[5];
    const float* b1    = (const float*)d_in[6];
    const float* W2    = (const float*)d_in[7];
    const float* b2    = (const float*)d_in[8];
    const float* gamma = (const float*)d_in[9];
    const float* beta  = (const float*)d_in[10];
    float* out = (float*)d_out;

    void *eaf, *weT, *w1T, *w2T, *aggr, *ag16, *h116, *h2, *sum_p, *sq_p;
    cudaGetSymbolAddress(&eaf, g_eaf16);
    cudaGetSymbolAddress(&weT, g_weT16);
    cudaGetSymbolAddress(&w1T, g_w1T16);
    cudaGetSymbolAddress(&w2T, g_w2T16);
    cudaGetSymbolAddress(&aggr, g_aggr);
    cudaGetSymbolAddress(&ag16, g_ag16);
    cudaGetSymbolAddress(&h116, g_h116);
    cudaGetSymbolAddress(&h2, g_h2);
    cudaGetSymbolAddress(&sum_p, g_sum);
    cudaGetSymbolAddress(&sq_p, g_sumsq);

    cudaFuncSetAttribute((const void*)mma_gemm_kernel<0>, cudaFuncAttributeMaxDynamicSharedMemorySize, SMEM_GEMM);
    cudaFuncSetAttribute((const void*)mma_gemm_kernel<1>, cudaFuncAttributeMaxDynamicSharedMemorySize, SMEM_GEMM);
    cudaFuncSetAttribute((const void*)mma_gemm_kernel<2>, cudaFuncAttributeMaxDynamicSharedMemorySize, SMEM_GEMM);

    // aggr = x (GIN eps=0); zero BN accumulators
    cudaMemcpyAsync(aggr, x, sizeof(float) * (size_t)NN * DIM, cudaMemcpyDeviceToDevice);
    cudaMemsetAsync(sum_p, 0, DIM * sizeof(float));
    cudaMemsetAsync(sq_p, 0, DIM * sizeof(float));

    // prep: eattr -> fp16; We/W1/W2 transposed -> fp16
    {
        size_t n4 = (size_t)NE * DIM / 4;
        tohalf_kernel<<<(unsigned)((n4 + 255) / 256), 256>>>(eattr, (__half*)eaf, n4);
        transpose_half_kernel<<<(DIM * DIM + 255) / 256, 256>>>(We, (__half*)weT);
        transpose_half_kernel<<<(DIM * DIM + 255) / 256, 256>>>(W1, (__half*)w1T);
        transpose_half_kernel<<<(DIM * DIM + 255) / 256, 256>>>(W2, (__half*)w2T);
    }

    // edge GEMM (fp16) + gather + relu + vector-red scatter-add
    mma_gemm_kernel<0><<<dim3(4, NE / 128), 128, SMEM_GEMM>>>(
        (const __half*)eaf, (const __half*)weT, be, NE, x, ei, (float*)aggr, nullptr);

    // aggr -> fp16
    {
        size_t n4 = (size_t)NN * DIM / 4;
        tohalf_kernel<<<(unsigned)((n4 + 255) / 256), 256>>>((const float*)aggr, (__half*)ag16, n4);
    }

    const int nrb = (NN + 127) / 128;
    // h1 = relu(aggr @ W1 + b1) -> fp16
    mma_gemm_kernel<1><<<dim3(4, nrb), 128, SMEM_GEMM>>>(
        (const __half*)ag16, (const __half*)w1T, b1, NN, nullptr, nullptr, nullptr, (__half*)h116);

    // h2 = h1 @ W2 + b2 -> fp32
    mma_gemm_kernel<2><<<dim3(4, nrb), 128, SMEM_GEMM>>>(
        (const __half*)h116, (const __half*)w2T, b2, NN, nullptr, nullptr, (float*)h2, nullptr);

    bn_stats_kernel<<<64, 256>>>();
    bn_finalize_kernel<<<2, 256>>>();

    const int n4 = NN * DIM / 4;
    bn_apply_kernel<<<(n4 + 255) / 256, 256>>>(gamma, beta, out);
}

// round 16
// speedup vs baseline: 1.6079x; 1.4643x over previous
#include <cuda_runtime.h>
#include <cuda_fp16.h>
#include <stdint.h>

#define DIM 512
#define NN 25000
#define NE 400000
#define BN_EPS 1e-5f

// ---------------- scratch (device globals; no runtime alloc) ----------------
__device__ __half g_eaf16[(size_t)NE * DIM];
__device__ __half g_weT16[DIM * DIM];
__device__ __half g_w1T16[DIM * DIM];
__device__ __half g_w2T16[DIM * DIM];
__device__ float g_aggr[(size_t)NN * DIM];
__device__ __half g_ag16[(size_t)NN * DIM];
__device__ __half g_h116[(size_t)NN * DIM];
__device__ float g_h2[(size_t)NN * DIM];
__device__ float g_sum[DIM], g_sumsq[DIM], g_mean[DIM], g_istd[DIM];

// ---------------- helpers ----------------
__device__ __forceinline__ uint32_t smem_u32(const void* p) {
    uint32_t a;
    asm("{ .reg .u64 t; cvta.to.shared.u64 t, %1; cvt.u32.u64 %0, t; }" : "=r"(a) : "l"(p));
    return a;
}
#define SW128(off) ((off) ^ (((off) >> 3) & 0x70))

__device__ __forceinline__ void cp16(uint32_t s, const void* g) {
    asm volatile("cp.async.cg.shared.global [%0], [%1], 16;" :: "r"(s), "l"(g));
}
__device__ __forceinline__ void ldm4(uint32_t* r, uint32_t a) {
    asm volatile("ldmatrix.sync.aligned.m8n8.x4.shared.b16 {%0,%1,%2,%3}, [%4];"
        : "=r"(r[0]), "=r"(r[1]), "=r"(r[2]), "=r"(r[3]) : "r"(a));
}
__device__ __forceinline__ void mma_f16(float* d, const uint32_t* a, const uint32_t* b) {
    asm volatile("mma.sync.aligned.m16n8k16.row.col.f32.f16.f16.f32 "
        "{%0,%1,%2,%3}, {%4,%5,%6,%7}, {%8,%9}, {%0,%1,%2,%3};"
        : "+f"(d[0]), "+f"(d[1]), "+f"(d[2]), "+f"(d[3])
        : "r"(a[0]), "r"(a[1]), "r"(a[2]), "r"(a[3]), "r"(b[0]), "r"(b[1]));
}
__device__ __forceinline__ void red_v4(float* p, float a, float b, float c, float d) {
    asm volatile("red.global.add.v4.f32 [%0], {%1, %2, %3, %4};"
        :: "l"(p), "f"(a), "f"(b), "f"(c), "f"(d) : "memory");
}

// ---------------- prep kernels ----------------
__global__ __launch_bounds__(256) void tohalf_kernel(const float* __restrict__ src,
                                                     __half* __restrict__ dst, size_t n4)
{
    size_t i = (size_t)blockIdx.x * blockDim.x + threadIdx.x;
    if (i < n4) {
        float4 v = reinterpret_cast<const float4*>(src)[i];
        reinterpret_cast<__half2*>(dst)[2 * i] = __floats2half2_rn(v.x, v.y);
        reinterpret_cast<__half2*>(dst)[2 * i + 1] = __floats2half2_rn(v.z, v.w);
    }
}

__global__ __launch_bounds__(256) void transpose_half_kernel(const float* __restrict__ W,
                                                             __half* __restrict__ d16)
{
    int i = blockIdx.x * blockDim.x + threadIdx.x;   // i = n*512 + k
    if (i < DIM * DIM) {
        int n = i >> 9, k = i & 511;
        d16[i] = __float2half_rn(W[k * DIM + n]);
    }
}

// ---------------- fp16 HMMA GEMM, 128x128 block, 32x64 warp tiles (R13 config) ----------
// 256 thr, 8 warps (4m x 2n), 3-stage cp.async pipeline, 2 CTAs/SM.
// MODE 0: edge: v = relu(acc + bias + x[src]); red.v4(aggr[dst], v)
// MODE 1: v = relu(acc + bias) -> fp16 store
// MODE 2: v = acc + bias -> fp32 store + fused BN column sums
#define STAGE_BYTES 32768            // A 16K + B 16K
#define SMEM_GEMM  (3 * STAGE_BYTES + 1024)   // + BN stat arrays (MODE 2)

template <int MODE>
__global__ __launch_bounds__(256, 2)
void mma_gemm_kernel(const __half* __restrict__ A,
                     const __half* __restrict__ B,    // transposed [N][K]
                     const float* __restrict__ bias,
                     int M,
                     const float* __restrict__ x,
                     const int* __restrict__ ei,
                     float* __restrict__ outf,
                     __half* __restrict__ outh)
{
    extern __shared__ char smem[];                    // 3 stages + 1KB stats
    const uint32_t sbase = smem_u32(smem);
    const int tid = threadIdx.x;
    const int wid = tid >> 5, lane = tid & 31;
    const int wm = wid & 3, wn = wid >> 2;
    const int row0 = blockIdx.y * 128;
    const int col0 = blockIdx.x * 128;

    float* ssum = reinterpret_cast<float*>(smem + 3 * STAGE_BYTES);        // [128]
    float* ssq  = reinterpret_cast<float*>(smem + 3 * STAGE_BYTES + 512);  // [128]
    if (MODE == 2 && tid < 128) { ssum[tid] = 0.f; ssq[tid] = 0.f; }

    float acc[2][8][4];
#pragma unroll
    for (int i = 0; i < 2; i++)
#pragma unroll
        for (int j = 0; j < 8; j++)
#pragma unroll
            for (int k = 0; k < 4; k++) acc[i][j][k] = 0.f;

    auto prefetch = [&](int c, int s) {
        const int k0 = c * 64;
        const uint32_t abase = sbase + (uint32_t)s * STAGE_BYTES;
        const uint32_t bbase = abase + 16384;
#pragma unroll
        for (int i = 0; i < 4; i++) {
            const int line = i * 256 + tid;           // 0..1023
            const int row = line >> 3, s16 = line & 7;
            const uint32_t so = SW128((uint32_t)(row * 128 + s16 * 16));
            int ar = row0 + row; if (ar >= M) ar = M - 1;
            cp16(abase + so, A + (size_t)ar * DIM + k0 + s16 * 8);
            cp16(bbase + so, B + (size_t)(col0 + row) * DIM + k0 + s16 * 8);
        }
        asm volatile("cp.async.commit_group;" ::: "memory");
    };

    auto compute = [&](int s) {
        const uint32_t abase = sbase + (uint32_t)s * STAGE_BYTES;
        const uint32_t bbase = abase + 16384;
#pragma unroll
        for (int kk = 0; kk < 4; kk++) {
            uint32_t a[2][4];
#pragma unroll
            for (int mt = 0; mt < 2; mt++) {
                const int r = wm * 32 + mt * 16 + (lane & 15);
                const uint32_t kb = (uint32_t)(kk * 32 + (lane >> 4) * 16);
                ldm4(a[mt], abase + SW128((uint32_t)(r * 128) + kb));
            }
            uint32_t b[8][2];
#pragma unroll
            for (int g = 0; g < 4; g++) {
                const int grp = lane >> 3;
                const int r = wn * 64 + g * 16 + (grp >> 1) * 8 + (lane & 7);
                const uint32_t kb = (uint32_t)(kk * 32 + (grp & 1) * 16);
                uint32_t t[4];
                ldm4(t, bbase + SW128((uint32_t)(r * 128) + kb));
                b[2 * g][0] = t[0]; b[2 * g][1] = t[1];
                b[2 * g + 1][0] = t[2]; b[2 * g + 1][1] = t[3];
            }
#pragma unroll
            for (int mt = 0; mt < 2; mt++)
#pragma unroll
                for (int nt = 0; nt < 8; nt++)
                    mma_f16(acc[mt][nt], a[mt], b[nt]);
        }
    };

    // 3-stage pipeline, prefetch depth 2, one sync per chunk.
    prefetch(0, 0);
    prefetch(1, 1);
    int sc = 0, sp = 2;
    for (int c = 0; c < 8; c++) {
        if (c == 7) {
            asm volatile("cp.async.wait_group 0;" ::: "memory");
        } else {
            asm volatile("cp.async.wait_group 1;" ::: "memory");
        }
        __syncthreads();
        if (c < 6) prefetch(c + 2, sp);
        compute(sc);
        sc = (sc == 2) ? 0 : sc + 1;
        sp = (sp == 2) ? 0 : sp + 1;
    }

    // ---------------- epilogue (direct from fragments) ----------------
    const int colbase = col0 + wn * 64;
#pragma unroll
    for (int mt = 0; mt < 2; mt++) {
#pragma unroll
        for (int h = 0; h < 2; h++) {
            const int r = row0 + wm * 32 + mt * 16 + h * 8 + (lane >> 2);
            if (MODE == 0) {
                const int src = ei[r];
                const int dst = ei[NE + r];
                const float* xr = x + (size_t)src * DIM;
                float* ap = outf + (size_t)dst * DIM;
#pragma unroll
                for (int nt = 0; nt < 8; nt++) {
                    const int c = colbase + nt * 8 + (lane & 3) * 2;
                    float2 xv = *reinterpret_cast<const float2*>(xr + c);
                    float v0 = fmaxf(acc[mt][nt][h * 2 + 0] + bias[c] + xv.x, 0.f);
                    float v1 = fmaxf(acc[mt][nt][h * 2 + 1] + bias[c + 1] + xv.y, 0.f);
                    float p0 = __shfl_xor_sync(0xFFFFFFFFu, v0, 1);
                    float p1 = __shfl_xor_sync(0xFFFFFFFFu, v1, 1);
                    if ((lane & 1) == 0)
                        red_v4(ap + c, v0, v1, p0, p1);
                }
            } else if (r < M) {
                if (MODE == 1) {
#pragma unroll
                    for (int nt = 0; nt < 8; nt++) {
                        const int c = colbase + nt * 8 + (lane & 3) * 2;
                        float v0 = fmaxf(acc[mt][nt][h * 2 + 0] + bias[c], 0.f);
                        float v1 = fmaxf(acc[mt][nt][h * 2 + 1] + bias[c + 1], 0.f);
                        *reinterpret_cast<__half2*>(outh + (size_t)r * DIM + c) =
                            __floats2half2_rn(v0, v1);
                    }
                } else {
#pragma unroll
                    for (int nt = 0; nt < 8; nt++) {
                        const int c = colbase + nt * 8 + (lane & 3) * 2;
                        float v0 = acc[mt][nt][h * 2 + 0] + bias[c];
                        float v1 = acc[mt][nt][h * 2 + 1] + bias[c + 1];
                        float2 v; v.x = v0; v.y = v1;
                        *reinterpret_cast<float2*>(outf + (size_t)r * DIM + c) = v;
                        const int lc = wn * 64 + nt * 8 + (lane & 3) * 2;   // 0..127
                        atomicAdd(&ssum[lc], v0);
                        atomicAdd(&ssum[lc + 1], v1);
                        atomicAdd(&ssq[lc], v0 * v0);
                        atomicAdd(&ssq[lc + 1], v1 * v1);
                    }
                }
            }
        }
    }

    if (MODE == 2) {
        __syncthreads();
        if (tid < 128) {
            atomicAdd(&g_sum[col0 + tid], ssum[tid]);
            atomicAdd(&g_sumsq[col0 + tid], ssq[tid]);
        }
    }
}

// ---------------- BN kernels ----------------
__global__ void bn_finalize_kernel()
{
    int c = blockIdx.x * blockDim.x + threadIdx.x;
    if (c < DIM) {
        float mean = g_sum[c] * (1.f / NN);
        float var = g_sumsq[c] * (1.f / NN) - mean * mean;
        g_mean[c] = mean;
        g_istd[c] = rsqrtf(var + BN_EPS);
    }
}

__global__ __launch_bounds__(256)
void bn_apply_kernel(const float* __restrict__ gamma,
                     const float* __restrict__ beta,
                     float* __restrict__ out)
{
    int idx = blockIdx.x * blockDim.x + threadIdx.x;
    if (idx >= NN * DIM / 4) return;
    const int c = (idx & (DIM / 4 - 1)) * 4;
    float4 h = reinterpret_cast<const float4*>(g_h2)[idx];
    float4 m = *reinterpret_cast<const float4*>(&g_mean[c]);
    float4 is = *reinterpret_cast<const float4*>(&g_istd[c]);
    float4 ga = *reinterpret_cast<const float4*>(&gamma[c]);
    float4 be = *reinterpret_cast<const float4*>(&beta[c]);
    float4 o;
    o.x = (h.x - m.x) * is.x * ga.x + be.x;
    o.y = (h.y - m.y) * is.y * ga.y + be.y;
    o.z = (h.z - m.z) * is.z * ga.z + be.z;
    o.w = (h.w - m.w) * is.w * ga.w + be.w;
    reinterpret_cast<float4*>(out)[idx] = o;
}

// ---------------- launch ----------------
extern "C" void kernel_launch(void* const* d_in, const int* in_sizes, int n_in,
                              void* d_out, int out_size)
{
    const float* x     = (const float*)d_in[0];
    const int*   ei    = (const int*)d_in[1];
    const float* eattr = (const float*)d_in[2];
    const float* We    = (const float*)d_in[3];
    const float* be    = (const float*)d_in[4];
    const float* W1    = (const float*)d_in[5];
    const float* b1    = (const float*)d_in[6];
    const float* W2    = (const float*)d_in[7];
    const float* b2    = (const float*)d_in[8];
    const float* gamma = (const float*)d_in[9];
    const float* beta  = (const float*)d_in[10];
    float* out = (float*)d_out;

    void *eaf, *weT, *w1T, *w2T, *aggr, *ag16, *h116, *h2, *sum_p, *sq_p;
    cudaGetSymbolAddress(&eaf, g_eaf16);
    cudaGetSymbolAddress(&weT, g_weT16);
    cudaGetSymbolAddress(&w1T, g_w1T16);
    cudaGetSymbolAddress(&w2T, g_w2T16);
    cudaGetSymbolAddress(&aggr, g_aggr);
    cudaGetSymbolAddress(&ag16, g_ag16);
    cudaGetSymbolAddress(&h116, g_h116);
    cudaGetSymbolAddress(&h2, g_h2);
    cudaGetSymbolAddress(&sum_p, g_sum);
    cudaGetSymbolAddress(&sq_p, g_sumsq);

    cudaFuncSetAttribute((const void*)mma_gemm_kernel<0>, cudaFuncAttributeMaxDynamicSharedMemorySize, SMEM_GEMM);
    cudaFuncSetAttribute((const void*)mma_gemm_kernel<1>, cudaFuncAttributeMaxDynamicSharedMemorySize, SMEM_GEMM);
    cudaFuncSetAttribute((const void*)mma_gemm_kernel<2>, cudaFuncAttributeMaxDynamicSharedMemorySize, SMEM_GEMM);

    // aggr = x (GIN eps=0); zero BN accumulators
    cudaMemcpyAsync(aggr, x, sizeof(float) * (size_t)NN * DIM, cudaMemcpyDeviceToDevice);
    cudaMemsetAsync(sum_p, 0, DIM * sizeof(float));
    cudaMemsetAsync(sq_p, 0, DIM * sizeof(float));

    // prep: eattr -> fp16; We/W1/W2 transposed -> fp16
    {
        size_t n4 = (size_t)NE * DIM / 4;
        tohalf_kernel<<<(unsigned)((n4 + 255) / 256), 256>>>(eattr, (__half*)eaf, n4);
        transpose_half_kernel<<<(DIM * DIM + 255) / 256, 256>>>(We, (__half*)weT);
        transpose_half_kernel<<<(DIM * DIM + 255) / 256, 256>>>(W1, (__half*)w1T);
        transpose_half_kernel<<<(DIM * DIM + 255) / 256, 256>>>(W2, (__half*)w2T);
    }

    // edge GEMM (fp16) + gather + relu + vector-red scatter-add
    mma_gemm_kernel<0><<<dim3(4, NE / 128), 256, SMEM_GEMM>>>(
        (const __half*)eaf, (const __half*)weT, be, NE, x, ei, (float*)aggr, nullptr);

    // aggr -> fp16
    {
        size_t n4 = (size_t)NN * DIM / 4;
        tohalf_kernel<<<(unsigned)((n4 + 255) / 256), 256>>>((const float*)aggr, (__half*)ag16, n4);
    }

    const int nrb = (NN + 127) / 128;
    // h1 = relu(aggr @ W1 + b1) -> fp16
    mma_gemm_kernel<1><<<dim3(4, nrb), 256, SMEM_GEMM>>>(
        (const __half*)ag16, (const __half*)w1T, b1, NN, nullptr, nullptr, nullptr, (__half*)h116);

    // h2 = h1 @ W2 + b2 -> fp32 (+ fused BN stats)
    mma_gemm_kernel<2><<<dim3(4, nrb), 256, SMEM_GEMM>>>(
        (const __half*)h116, (const __half*)w2T, b2, NN, nullptr, nullptr, (float*)h2, nullptr);

    bn_finalize_kernel<<<2, 256>>>();

    const int n4 = NN * DIM / 4;
    bn_apply_kernel<<<(n4 + 255) / 256, 256>>>(gamma, beta, out);
}

// round 17
// speedup vs baseline: 1.8840x; 1.1717x over previous
#include <cuda_runtime.h>
#include <cuda_fp16.h>
#include <stdint.h>

#define DIM 512
#define NN 25000
#define NE 400000
#define BN_EPS 1e-5f

// ---------------- scratch (device globals; no runtime alloc) ----------------
__device__ __half g_eaf16[(size_t)NE * DIM];
__device__ __half g_weT16[DIM * DIM];
__device__ __half g_w1T16[DIM * DIM];
__device__ __half g_w2T16[DIM * DIM];
__device__ float g_aggr[(size_t)NN * DIM];
__device__ __half g_ag16[(size_t)NN * DIM];
__device__ __half g_h116[(size_t)NN * DIM];
__device__ float g_h2[(size_t)NN * DIM];
__device__ float g_sum[DIM], g_sumsq[DIM], g_mean[DIM], g_istd[DIM];

// ---------------- helpers ----------------
__device__ __forceinline__ uint32_t smem_u32(const void* p) {
    uint32_t a;
    asm("{ .reg .u64 t; cvta.to.shared.u64 t, %1; cvt.u32.u64 %0, t; }" : "=r"(a) : "l"(p));
    return a;
}
#define SW128(off) ((off) ^ (((off) >> 3) & 0x70))

__device__ __forceinline__ void cp16(uint32_t s, const void* g) {
    asm volatile("cp.async.cg.shared.global [%0], [%1], 16;" :: "r"(s), "l"(g));
}
__device__ __forceinline__ void ldm4(uint32_t* r, uint32_t a) {
    asm volatile("ldmatrix.sync.aligned.m8n8.x4.shared.b16 {%0,%1,%2,%3}, [%4];"
        : "=r"(r[0]), "=r"(r[1]), "=r"(r[2]), "=r"(r[3]) : "r"(a));
}
__device__ __forceinline__ void mma_f16(float* d, const uint32_t* a, const uint32_t* b) {
    asm volatile("mma.sync.aligned.m16n8k16.row.col.f32.f16.f16.f32 "
        "{%0,%1,%2,%3}, {%4,%5,%6,%7}, {%8,%9}, {%0,%1,%2,%3};"
        : "+f"(d[0]), "+f"(d[1]), "+f"(d[2]), "+f"(d[3])
        : "r"(a[0]), "r"(a[1]), "r"(a[2]), "r"(a[3]), "r"(b[0]), "r"(b[1]));
}
__device__ __forceinline__ void red_v4(float* p, float a, float b, float c, float d) {
    asm volatile("red.global.add.v4.f32 [%0], {%1, %2, %3, %4};"
        :: "l"(p), "f"(a), "f"(b), "f"(c), "f"(d) : "memory");
}

// ---------------- prep kernels ----------------
__global__ __launch_bounds__(256) void tohalf_kernel(const float* __restrict__ src,
                                                     __half* __restrict__ dst, size_t n4)
{
    size_t i = (size_t)blockIdx.x * blockDim.x + threadIdx.x;
    if (i < n4) {
        float4 v = reinterpret_cast<const float4*>(src)[i];
        reinterpret_cast<__half2*>(dst)[2 * i] = __floats2half2_rn(v.x, v.y);
        reinterpret_cast<__half2*>(dst)[2 * i + 1] = __floats2half2_rn(v.z, v.w);
    }
}

__global__ __launch_bounds__(256) void transpose_half_kernel(const float* __restrict__ W,
                                                             __half* __restrict__ d16)
{
    int i = blockIdx.x * blockDim.x + threadIdx.x;   // i = n*512 + k
    if (i < DIM * DIM) {
        int n = i >> 9, k = i & 511;
        d16[i] = __float2half_rn(W[k * DIM + n]);
    }
}

// ---------------- fp16 HMMA GEMM, 128x128 block, 32x64 warp tiles (R13 config) ----------
// 256 thr, 8 warps (4m x 2n), 3-stage cp.async pipeline, 2 CTAs/SM.
// MODE 0: edge: v = relu(acc + bias + x[src]); red.v4(aggr[dst], v)
// MODE 1: v = relu(acc + bias) -> fp16 store
// MODE 2: v = acc + bias -> fp32 store + BN stats via shfl-reduce + global red
#define STAGE_BYTES 32768            // A 16K + B 16K
#define SMEM_GEMM  (3 * STAGE_BYTES)

template <int MODE>
__global__ __launch_bounds__(256, 2)
void mma_gemm_kernel(const __half* __restrict__ A,
                     const __half* __restrict__ B,    // transposed [N][K]
                     const float* __restrict__ bias,
                     int M,
                     const float* __restrict__ x,
                     const int* __restrict__ ei,
                     float* __restrict__ outf,
                     __half* __restrict__ outh)
{
    extern __shared__ char smem[];                    // 3 x (A 16K + B 16K)
    const uint32_t sbase = smem_u32(smem);
    const int tid = threadIdx.x;
    const int wid = tid >> 5, lane = tid & 31;
    const int wm = wid & 3, wn = wid >> 2;
    const int row0 = blockIdx.y * 128;
    const int col0 = blockIdx.x * 128;

    float acc[2][8][4];
#pragma unroll
    for (int i = 0; i < 2; i++)
#pragma unroll
        for (int j = 0; j < 8; j++)
#pragma unroll
            for (int k = 0; k < 4; k++) acc[i][j][k] = 0.f;

    auto prefetch = [&](int c, int s) {
        const int k0 = c * 64;
        const uint32_t abase = sbase + (uint32_t)s * STAGE_BYTES;
        const uint32_t bbase = abase + 16384;
#pragma unroll
        for (int i = 0; i < 4; i++) {
            const int line = i * 256 + tid;           // 0..1023
            const int row = line >> 3, s16 = line & 7;
            const uint32_t so = SW128((uint32_t)(row * 128 + s16 * 16));
            int ar = row0 + row; if (ar >= M) ar = M - 1;
            cp16(abase + so, A + (size_t)ar * DIM + k0 + s16 * 8);
            cp16(bbase + so, B + (size_t)(col0 + row) * DIM + k0 + s16 * 8);
        }
        asm volatile("cp.async.commit_group;" ::: "memory");
    };

    auto compute = [&](int s) {
        const uint32_t abase = sbase + (uint32_t)s * STAGE_BYTES;
        const uint32_t bbase = abase + 16384;
#pragma unroll
        for (int kk = 0; kk < 4; kk++) {
            uint32_t a[2][4];
#pragma unroll
            for (int mt = 0; mt < 2; mt++) {
                const int r = wm * 32 + mt * 16 + (lane & 15);
                const uint32_t kb = (uint32_t)(kk * 32 + (lane >> 4) * 16);
                ldm4(a[mt], abase + SW128((uint32_t)(r * 128) + kb));
            }
            uint32_t b[8][2];
#pragma unroll
            for (int g = 0; g < 4; g++) {
                const int grp = lane >> 3;
                const int r = wn * 64 + g * 16 + (grp >> 1) * 8 + (lane & 7);
                const uint32_t kb = (uint32_t)(kk * 32 + (grp & 1) * 16);
                uint32_t t[4];
                ldm4(t, bbase + SW128((uint32_t)(r * 128) + kb));
                b[2 * g][0] = t[0]; b[2 * g][1] = t[1];
                b[2 * g + 1][0] = t[2]; b[2 * g + 1][1] = t[3];
            }
#pragma unroll
            for (int mt = 0; mt < 2; mt++)
#pragma unroll
                for (int nt = 0; nt < 8; nt++)
                    mma_f16(acc[mt][nt], a[mt], b[nt]);
        }
    };

    // 3-stage pipeline, prefetch depth 2, one sync per chunk.
    prefetch(0, 0);
    prefetch(1, 1);
    int sc = 0, sp = 2;
    for (int c = 0; c < 8; c++) {
        if (c == 7) {
            asm volatile("cp.async.wait_group 0;" ::: "memory");
        } else {
            asm volatile("cp.async.wait_group 1;" ::: "memory");
        }
        __syncthreads();
        if (c < 6) prefetch(c + 2, sp);
        compute(sc);
        sc = (sc == 2) ? 0 : sc + 1;
        sp = (sp == 2) ? 0 : sp + 1;
    }

    // ---------------- epilogue (direct from fragments) ----------------
    const int colbase = col0 + wn * 64;
    if (MODE == 2) {
        // nt outer; accumulate column stats in 4 regs, shfl-reduce, global red.
#pragma unroll
        for (int nt = 0; nt < 8; nt++) {
            const int c = colbase + nt * 8 + (lane & 3) * 2;
            const float b0 = bias[c], b1 = bias[c + 1];
            float s0 = 0.f, s1 = 0.f, q0 = 0.f, q1 = 0.f;
#pragma unroll
            for (int mt = 0; mt < 2; mt++) {
#pragma unroll
                for (int h = 0; h < 2; h++) {
                    const int r = row0 + wm * 32 + mt * 16 + h * 8 + (lane >> 2);
                    if (r < M) {
                        float v0 = acc[mt][nt][h * 2 + 0] + b0;
                        float v1 = acc[mt][nt][h * 2 + 1] + b1;
                        float2 v; v.x = v0; v.y = v1;
                        *reinterpret_cast<float2*>(outf + (size_t)r * DIM + c) = v;
                        s0 += v0; s1 += v1;
                        q0 = fmaf(v0, v0, q0); q1 = fmaf(v1, v1, q1);
                    }
                }
            }
#pragma unroll
            for (int o = 4; o < 32; o <<= 1) {
                s0 += __shfl_xor_sync(0xFFFFFFFFu, s0, o);
                s1 += __shfl_xor_sync(0xFFFFFFFFu, s1, o);
                q0 += __shfl_xor_sync(0xFFFFFFFFu, q0, o);
                q1 += __shfl_xor_sync(0xFFFFFFFFu, q1, o);
            }
            if (lane < 4) {
                atomicAdd(&g_sum[c], s0);
                atomicAdd(&g_sum[c + 1], s1);
                atomicAdd(&g_sumsq[c], q0);
                atomicAdd(&g_sumsq[c + 1], q1);
            }
        }
    } else {
#pragma unroll
        for (int mt = 0; mt < 2; mt++) {
#pragma unroll
            for (int h = 0; h < 2; h++) {
                const int r = row0 + wm * 32 + mt * 16 + h * 8 + (lane >> 2);
                if (MODE == 0) {
                    const int src = ei[r];
                    const int dst = ei[NE + r];
                    const float* xr = x + (size_t)src * DIM;
                    float* ap = outf + (size_t)dst * DIM;
#pragma unroll
                    for (int nt = 0; nt < 8; nt++) {
                        const int c = colbase + nt * 8 + (lane & 3) * 2;
                        float2 xv = *reinterpret_cast<const float2*>(xr + c);
                        float v0 = fmaxf(acc[mt][nt][h * 2 + 0] + bias[c] + xv.x, 0.f);
                        float v1 = fmaxf(acc[mt][nt][h * 2 + 1] + bias[c + 1] + xv.y, 0.f);
                        float p0 = __shfl_xor_sync(0xFFFFFFFFu, v0, 1);
                        float p1 = __shfl_xor_sync(0xFFFFFFFFu, v1, 1);
                        if ((lane & 1) == 0)
                            red_v4(ap + c, v0, v1, p0, p1);
                    }
                } else if (r < M) {
#pragma unroll
                    for (int nt = 0; nt < 8; nt++) {
                        const int c = colbase + nt * 8 + (lane & 3) * 2;
                        float v0 = fmaxf(acc[mt][nt][h * 2 + 0] + bias[c], 0.f);
                        float v1 = fmaxf(acc[mt][nt][h * 2 + 1] + bias[c + 1], 0.f);
                        *reinterpret_cast<__half2*>(outh + (size_t)r * DIM + c) =
                            __floats2half2_rn(v0, v1);
                    }
                }
            }
        }
    }
}

// ---------------- BN kernels ----------------
__global__ void bn_finalize_kernel()
{
    int c = blockIdx.x * blockDim.x + threadIdx.x;
    if (c < DIM) {
        float mean = g_sum[c] * (1.f / NN);
        float var = g_sumsq[c] * (1.f / NN) - mean * mean;
        g_mean[c] = mean;
        g_istd[c] = rsqrtf(var + BN_EPS);
    }
}

__global__ __launch_bounds__(256)
void bn_apply_kernel(const float* __restrict__ gamma,
                     const float* __restrict__ beta,
                     float* __restrict__ out)
{
    int idx = blockIdx.x * blockDim.x + threadIdx.x;
    if (idx >= NN * DIM / 4) return;
    const int c = (idx & (DIM / 4 - 1)) * 4;
    float4 h = reinterpret_cast<const float4*>(g_h2)[idx];
    float4 m = *reinterpret_cast<const float4*>(&g_mean[c]);
    float4 is = *reinterpret_cast<const float4*>(&g_istd[c]);
    float4 ga = *reinterpret_cast<const float4*>(&gamma[c]);
    float4 be = *reinterpret_cast<const float4*>(&beta[c]);
    float4 o;
    o.x = (h.x - m.x) * is.x * ga.x + be.x;
    o.y = (h.y - m.y) * is.y * ga.y + be.y;
    o.z = (h.z - m.z) * is.z * ga.z + be.z;
    o.w = (h.w - m.w) * is.w * ga.w + be.w;
    reinterpret_cast<float4*>(out)[idx] = o;
}

// ---------------- launch ----------------
extern "C" void kernel_launch(void* const* d_in, const int* in_sizes, int n_in,
                              void* d_out, int out_size)
{
    const float* x     = (const float*)d_in[0];
    const int*   ei    = (const int*)d_in[1];
    const float* eattr = (const float*)d_in[2];
    const float* We    = (const float*)d_in[3];
    const float* be    = (const float*)d_in[4];
    const float* W1    = (const float*)d_in[5];
    const float* b1    = (const float*)d_in[6];
    const float* W2    = (const float*)d_in[7];
    const float* b2    = (const float*)d_in[8];
    const float* gamma = (const float*)d_in[9];
    const float* beta  = (const float*)d_in[10];
    float* out = (float*)d_out;

    void *eaf, *weT, *w1T, *w2T, *aggr, *ag16, *h116, *h2, *sum_p, *sq_p;
    cudaGetSymbolAddress(&eaf, g_eaf16);
    cudaGetSymbolAddress(&weT, g_weT16);
    cudaGetSymbolAddress(&w1T, g_w1T16);
    cudaGetSymbolAddress(&w2T, g_w2T16);
    cudaGetSymbolAddress(&aggr, g_aggr);
    cudaGetSymbolAddress(&ag16, g_ag16);
    cudaGetSymbolAddress(&h116, g_h116);
    cudaGetSymbolAddress(&h2, g_h2);
    cudaGetSymbolAddress(&sum_p, g_sum);
    cudaGetSymbolAddress(&sq_p, g_sumsq);

    cudaFuncSetAttribute((const void*)mma_gemm_kernel<0>, cudaFuncAttributeMaxDynamicSharedMemorySize, SMEM_GEMM);
    cudaFuncSetAttribute((const void*)mma_gemm_kernel<1>, cudaFuncAttributeMaxDynamicSharedMemorySize, SMEM_GEMM);
    cudaFuncSetAttribute((const void*)mma_gemm_kernel<2>, cudaFuncAttributeMaxDynamicSharedMemorySize, SMEM_GEMM);

    // aggr = x (GIN eps=0); zero BN accumulators
    cudaMemcpyAsync(aggr, x, sizeof(float) * (size_t)NN * DIM, cudaMemcpyDeviceToDevice);
    cudaMemsetAsync(sum_p, 0, DIM * sizeof(float));
    cudaMemsetAsync(sq_p, 0, DIM * sizeof(float));

    // prep: eattr -> fp16; We/W1/W2 transposed -> fp16
    {
        size_t n4 = (size_t)NE * DIM / 4;
        tohalf_kernel<<<(unsigned)((n4 + 255) / 256), 256>>>(eattr, (__half*)eaf, n4);
        transpose_half_kernel<<<(DIM * DIM + 255) / 256, 256>>>(We, (__half*)weT);
        transpose_half_kernel<<<(DIM * DIM + 255) / 256, 256>>>(W1, (__half*)w1T);
        transpose_half_kernel<<<(DIM * DIM + 255) / 256, 256>>>(W2, (__half*)w2T);
    }

    // edge GEMM (fp16) + gather + relu + vector-red scatter-add
    mma_gemm_kernel<0><<<dim3(4, NE / 128), 256, SMEM_GEMM>>>(
        (const __half*)eaf, (const __half*)weT, be, NE, x, ei, (float*)aggr, nullptr);

    // aggr -> fp16
    {
        size_t n4 = (size_t)NN * DIM / 4;
        tohalf_kernel<<<(unsigned)((n4 + 255) / 256), 256>>>((const float*)aggr, (__half*)ag16, n4);
    }

    const int nrb = (NN + 127) / 128;
    // h1 = relu(aggr @ W1 + b1) -> fp16
    mma_gemm_kernel<1><<<dim3(4, nrb), 256, SMEM_GEMM>>>(
        (const __half*)ag16, (const __half*)w1T, b1, NN, nullptr, nullptr, nullptr, (__half*)h116);

    // h2 = h1 @ W2 + b2 -> fp32 (+ fused BN stats via shfl reduce)
    mma_gemm_kernel<2><<<dim3(4, nrb), 256, SMEM_GEMM>>>(
        (const __half*)h116, (const __half*)w2T, b2, NN, nullptr, nullptr, (float*)h2, nullptr);

    bn_finalize_kernel<<<2, 256>>>();

    const int n4 = NN * DIM / 4;
    bn_apply_kernel<<<(n4 + 255) / 256, 256>>>(gamma, beta, out);
}